// round 3
// baseline (speedup 1.0000x reference)
#include <cuda_runtime.h>

#define N_      16384
#define K_      64
#define F_      2048
#define NCHUNK  4
#define CHUNK   512          // floats per F-chunk (256 threads x float2)
#define ALPHA_F 1.0f
#define GAMMA_F 1.0f

// ---- scratch (static device globals: allocation-free) ----
__device__ int   g_idx[N_];
__device__ int   g_rows[K_ * N_];     // per-cluster member row lists (stride N_)
__device__ int   g_cnt[K_];
__device__ float g_csum[F_];
__device__ float g_norm[K_];
__device__ float g_dot[K_];
__device__ float g_ak[K_];            // cw[k] / (row_sum[k]+alpha)
__device__ float g_invden[K_];        // 1 / (row_sum[k]+alpha)

// csum[f] = sum_k C[k,f]
__global__ void csum_k(const float* __restrict__ C) {
    int col = blockIdx.x * blockDim.x + threadIdx.x;
    float s = 0.f;
#pragma unroll
    for (int k = 0; k < K_; k++) s += C[k * F_ + col];
    g_csum[col] = s;
}

// per-k: norm[k] = ||c_k||^2,  dot[k] = c_k . csum
__global__ void normdot_k(const float* __restrict__ C) {
    int k = blockIdx.x, tid = threadIdx.x;
    float nn = 0.f, dd = 0.f;
    for (int f = tid; f < F_; f += 256) {
        float c = C[k * F_ + f];
        nn += c * c;
        dd += c * g_csum[f];
    }
#pragma unroll
    for (int o = 16; o; o >>= 1) {
        nn += __shfl_xor_sync(0xFFFFFFFFu, nn, o);
        dd += __shfl_xor_sync(0xFFFFFFFFu, dd, o);
    }
    __shared__ float sn[8], sd[8];
    int w = tid >> 5, l = tid & 31;
    if (l == 0) { sn[w] = nn; sd[w] = dd; }
    __syncthreads();
    if (tid == 0) {
        float a = 0.f, b = 0.f;
#pragma unroll
        for (int i = 0; i < 8; i++) { a += sn[i]; b += sd[i]; }
        g_norm[k] = a; g_dot[k] = b;
    }
}

// row_sum[k] = K*norm[k] + sum(norm) - 2*dot[k];  a_k, invden
__global__ void finalize_k(const float* __restrict__ cw) {
    __shared__ float tot;
    int t = threadIdx.x;           // 64 threads
    if (t == 0) {
        float s = 0.f;
        for (int i = 0; i < K_; i++) s += g_norm[i];
        tot = s;
    }
    __syncthreads();
    float rs  = (float)K_ * g_norm[t] + tot - 2.f * g_dot[t];
    float inv = 1.f / (rs + ALPHA_F);
    g_invden[t] = inv;
    g_ak[t]     = cw[t] * inv;
}

// warp-per-row argmax of one-hot labels (exact 1.0f -> ballot on >0.5)
// also zero-init the loss region of d_out (poisoned by harness)
__global__ void idx_k(const float* __restrict__ labels, float* __restrict__ loss) {
    int tid = threadIdx.x;
    int w = tid >> 5, l = tid & 31;
    int row = blockIdx.x * 8 + w;
    float v0 = labels[row * K_ + l];
    float v1 = labels[row * K_ + 32 + l];
    unsigned b0 = __ballot_sync(0xFFFFFFFFu, v0 > 0.5f);
    unsigned b1 = __ballot_sync(0xFFFFFFFFu, v1 > 0.5f);
    int id = b0 ? (__ffs(b0) - 1) : (31 + __ffs(b1));
    if (l == 0) { g_idx[row] = id; loss[row] = 0.f; }
}

// stable (deterministic) compaction: block k gathers its member rows in order
__global__ void bucket_k() {
    int k = blockIdx.x, tid = threadIdx.x;
    int w = tid >> 5, l = tid & 31;
    __shared__ int wcnt[8];
    unsigned lmask = (1u << l) - 1u;
    int base = 0;                       // every thread tracks base identically
    for (int t0 = 0; t0 < N_; t0 += 256) {
        int n = t0 + tid;
        int pred = (g_idx[n] == k);
        unsigned b = __ballot_sync(0xFFFFFFFFu, pred);
        if (l == 0) wcnt[w] = __popc(b);
        __syncthreads();
        int woff = 0, tot = 0;
#pragma unroll
        for (int j = 0; j < 8; j++) { int c = wcnt[j]; tot += c; if (j < w) woff += c; }
        if (pred) g_rows[k * N_ + base + woff + __popc(b & lmask)] = n;
        base += tot;
        __syncthreads();                // protect wcnt reuse next iter
    }
    if (tid == 0) g_cnt[k] = base;
}

// main fused pass: block (chunk c, cluster k); thread owns float2 column pair.
// - accumulates Sx[k, cols] in registers
// - per-row ||x-c||^2 partial -> warp reduce -> atomicAdd(loss[n], s*invden_k)
// - epilogue writes new_cluster[k, cols] directly (exclusive ownership)
__global__ void __launch_bounds__(256) main_k(const float* __restrict__ X,
                                              const float* __restrict__ C,
                                              float* __restrict__ out) {
    int c   = blockIdx.x;
    int k   = blockIdx.y;
    int tid = threadIdx.x;
    int l   = tid & 31;
    int col = c * CHUNK + 2 * tid;

    float2 ck = *(const float2*)(C + k * F_ + col);
    float ax = 0.f, ay = 0.f;
    int   cnt  = g_cnt[k];
    float invd = g_invden[k];
    float* loss = out;                              // loss lives at out[0..N)

    __shared__ int srows[64];
    const int* rl = g_rows + k * N_;

    for (int rb = 0; rb < cnt; rb += 64) {
        int m = min(64, cnt - rb);
        if (tid < m) srows[tid] = rl[rb + tid];
        __syncthreads();
#pragma unroll 4
        for (int i = 0; i < m; i++) {
            int n = srows[i];
            float2 x = *(const float2*)(X + (size_t)n * F_ + col);
            float dx = x.x - ck.x, dy = x.y - ck.y;
            float s = dx * dx + dy * dy;
            ax += x.x; ay += x.y;
#pragma unroll
            for (int o = 16; o; o >>= 1) s += __shfl_xor_sync(0xFFFFFFFFu, s, o);
            if (l == 0) atomicAdd(loss + n, s * invd);
        }
        __syncthreads();
    }

    float ak = g_ak[k];
    float fc = (float)cnt;
    float2 o;
    o.x = ck.x - GAMMA_F * ak * (ax - fc * ck.x);
    o.y = ck.y - GAMMA_F * ak * (ay - fc * ck.y);
    *(float2*)(out + N_ + k * F_ + col) = o;
}

extern "C" void kernel_launch(void* const* d_in, const int* in_sizes, int n_in,
                              void* d_out, int out_size) {
    const float* X  = (const float*)d_in[0];   // features [N,F]
    const float* L  = (const float*)d_in[1];   // labels   [N,K] one-hot
    const float* C  = (const float*)d_in[2];   // cluster  [K,F]
    const float* CW = (const float*)d_in[3];   // class_weight [K]
    float* out = (float*)d_out;                // [loss(N) | new_cluster(K*F)]

    csum_k    <<<F_ / 256, 256>>>(C);
    normdot_k <<<K_, 256>>>(C);
    finalize_k<<<1, K_>>>(CW);
    idx_k     <<<N_ / 8, 256>>>(L, out);
    bucket_k  <<<K_, 256>>>();
    main_k    <<<dim3(NCHUNK, K_), 256>>>(X, C, out);
}